// round 1
// baseline (speedup 1.0000x reference)
#include <cuda_runtime.h>
#include <cstddef>

// Problem constants
#define BV 4      // batch
#define CC 256    // channels
#define CQ 128    // q/k channels
#define NN 4096   // pixels (64*64)

// Scratch (device globals: allocation at module load, allowed by harness rules)
__device__ float g_q[(size_t)BV * CQ * NN];       // 8 MiB
__device__ float g_k[(size_t)BV * CQ * NN];       // 8 MiB
__device__ float g_v[(size_t)BV * CC * NN];       // 16 MiB
__device__ float g_p[(size_t)BV * NN * NN];       // 256 MiB (scores -> attn, in place)

// GEMM tiling
#define BM 128
#define BN 128
#define BK 8

// ---------------------------------------------------------------------------
// proj: dst[b,m,n] = sum_k W[m,k] * x[b,k,n] + bias[m]
//   W row-major [M, CC], x [CC, NN] per batch. sel: 0->g_q, 1->g_k, 2->g_v
// ---------------------------------------------------------------------------
__global__ __launch_bounds__(256) void proj_kernel(
    const float* __restrict__ W, const float* __restrict__ bias,
    const float* __restrict__ x, int M, int sel)
{
    float* dst = (sel == 0) ? g_q : (sel == 1) ? g_k : g_v;
    const int b = blockIdx.z;
    const float* Bg = x + (size_t)b * CC * NN;
    float*       Cg = dst + (size_t)b * M * NN;
    const int m0 = blockIdx.y * BM, n0 = blockIdx.x * BN;

    __shared__ __align__(16) float As[BK][BM];
    __shared__ __align__(16) float Bs[BK][BN];

    const int tid = threadIdx.x;
    const int tx = tid & 15, ty = tid >> 4;

    float acc[8][8];
    #pragma unroll
    for (int i = 0; i < 8; i++)
        #pragma unroll
        for (int j = 0; j < 8; j++) acc[i][j] = 0.f;

    const int arow = tid >> 1;          // 0..127
    const int agrp = (tid & 1) * 4;     // 0 or 4
    const int bkk  = (tid * 4) >> 7;    // 0..7
    const int bnn  = (tid * 4) & 127;   // 0..124

    for (int k0 = 0; k0 < CC; k0 += BK) {
        float4 a = *(const float4*)&W[(size_t)(m0 + arow) * CC + k0 + agrp];
        As[agrp + 0][arow] = a.x;
        As[agrp + 1][arow] = a.y;
        As[agrp + 2][arow] = a.z;
        As[agrp + 3][arow] = a.w;
        *(float4*)&Bs[bkk][bnn] =
            *(const float4*)&Bg[(size_t)(k0 + bkk) * NN + n0 + bnn];
        __syncthreads();

        #pragma unroll
        for (int kk = 0; kk < BK; kk++) {
            float av[8], bv[8];
            *(float4*)&av[0] = *(float4*)&As[kk][ty * 8];
            *(float4*)&av[4] = *(float4*)&As[kk][ty * 8 + 4];
            *(float4*)&bv[0] = *(float4*)&Bs[kk][tx * 8];
            *(float4*)&bv[4] = *(float4*)&Bs[kk][tx * 8 + 4];
            #pragma unroll
            for (int i = 0; i < 8; i++)
                #pragma unroll
                for (int j = 0; j < 8; j++)
                    acc[i][j] += av[i] * bv[j];
        }
        __syncthreads();
    }

    #pragma unroll
    for (int i = 0; i < 8; i++) {
        const float bi = bias[m0 + ty * 8 + i];
        float* crow = &Cg[(size_t)(m0 + ty * 8 + i) * NN + n0 + tx * 8];
        float4 r0, r1;
        r0.x = acc[i][0] + bi; r0.y = acc[i][1] + bi;
        r0.z = acc[i][2] + bi; r0.w = acc[i][3] + bi;
        r1.x = acc[i][4] + bi; r1.y = acc[i][5] + bi;
        r1.z = acc[i][6] + bi; r1.w = acc[i][7] + bi;
        *(float4*)&crow[0] = r0;
        *(float4*)&crow[4] = r1;
    }
}

// ---------------------------------------------------------------------------
// scores: S[b,m,n] = sum_d q[b,d,m] * k[b,d,n]   (both K-major, K = CQ = 128)
// ---------------------------------------------------------------------------
__global__ __launch_bounds__(256) void scores_kernel()
{
    const int b = blockIdx.z;
    const float* Ag = g_q + (size_t)b * CQ * NN;
    const float* Bg = g_k + (size_t)b * CQ * NN;
    float*       Cg = g_p + (size_t)b * NN * NN;
    const int m0 = blockIdx.y * BM, n0 = blockIdx.x * BN;

    __shared__ __align__(16) float As[BK][BM];
    __shared__ __align__(16) float Bs[BK][BN];

    const int tid = threadIdx.x;
    const int tx = tid & 15, ty = tid >> 4;

    float acc[8][8];
    #pragma unroll
    for (int i = 0; i < 8; i++)
        #pragma unroll
        for (int j = 0; j < 8; j++) acc[i][j] = 0.f;

    const int lkk = (tid * 4) >> 7;
    const int lmm = (tid * 4) & 127;

    for (int k0 = 0; k0 < CQ; k0 += BK) {
        *(float4*)&As[lkk][lmm] =
            *(const float4*)&Ag[(size_t)(k0 + lkk) * NN + m0 + lmm];
        *(float4*)&Bs[lkk][lmm] =
            *(const float4*)&Bg[(size_t)(k0 + lkk) * NN + n0 + lmm];
        __syncthreads();

        #pragma unroll
        for (int kk = 0; kk < BK; kk++) {
            float av[8], bv[8];
            *(float4*)&av[0] = *(float4*)&As[kk][ty * 8];
            *(float4*)&av[4] = *(float4*)&As[kk][ty * 8 + 4];
            *(float4*)&bv[0] = *(float4*)&Bs[kk][tx * 8];
            *(float4*)&bv[4] = *(float4*)&Bs[kk][tx * 8 + 4];
            #pragma unroll
            for (int i = 0; i < 8; i++)
                #pragma unroll
                for (int j = 0; j < 8; j++)
                    acc[i][j] += av[i] * bv[j];
        }
        __syncthreads();
    }

    #pragma unroll
    for (int i = 0; i < 8; i++) {
        float* crow = &Cg[(size_t)(m0 + ty * 8 + i) * NN + n0 + tx * 8];
        *(float4*)&crow[0] = *(float4*)&acc[i][0];
        *(float4*)&crow[4] = *(float4*)&acc[i][4];
    }
}

// ---------------------------------------------------------------------------
// softmax over last axis, in place on g_p. One block per row (4096 floats).
// ---------------------------------------------------------------------------
__global__ __launch_bounds__(256) void softmax_kernel()
{
    const size_t row = blockIdx.x;
    float* p = g_p + row * (size_t)NN;
    const int tid = threadIdx.x;
    const int lane = tid & 31, wid = tid >> 5;

    __shared__ float red[32];

    float4 v[4];
    float mx = -1e30f;
    #pragma unroll
    for (int i = 0; i < 4; i++) {
        v[i] = *(const float4*)&p[i * 1024 + tid * 4];
        mx = fmaxf(mx, fmaxf(fmaxf(v[i].x, v[i].y), fmaxf(v[i].z, v[i].w)));
    }
    #pragma unroll
    for (int o = 16; o; o >>= 1) mx = fmaxf(mx, __shfl_xor_sync(0xffffffffu, mx, o));
    if (lane == 0) red[wid] = mx;
    __syncthreads();
    if (tid == 0) {
        float m = red[0];
        #pragma unroll
        for (int i = 1; i < 8; i++) m = fmaxf(m, red[i]);
        red[0] = m;
    }
    __syncthreads();
    mx = red[0];
    __syncthreads();   // protect red[] reuse

    float s = 0.f;
    #pragma unroll
    for (int i = 0; i < 4; i++) {
        v[i].x = __expf(v[i].x - mx);
        v[i].y = __expf(v[i].y - mx);
        v[i].z = __expf(v[i].z - mx);
        v[i].w = __expf(v[i].w - mx);
        s += v[i].x + v[i].y + v[i].z + v[i].w;
    }
    #pragma unroll
    for (int o = 16; o; o >>= 1) s += __shfl_xor_sync(0xffffffffu, s, o);
    if (lane == 0) red[wid] = s;
    __syncthreads();
    if (tid == 0) {
        float t = 0.f;
        #pragma unroll
        for (int i = 0; i < 8; i++) t += red[i];
        red[0] = t;
    }
    __syncthreads();
    const float inv = 1.0f / red[0];

    #pragma unroll
    for (int i = 0; i < 4; i++) {
        v[i].x *= inv; v[i].y *= inv; v[i].z *= inv; v[i].w *= inv;
        *(float4*)&p[i * 1024 + tid * 4] = v[i];
    }
}

// ---------------------------------------------------------------------------
// av: out[b,c,j] = gamma * sum_i v[b,c,i] * P[b,i,j] + x[b,c,j]
//   V row-major [CC, NN], P [NN, NN]. K = NN = 4096.
// ---------------------------------------------------------------------------
__global__ __launch_bounds__(256) void av_kernel(
    const float* __restrict__ x, const float* __restrict__ gamma,
    float* __restrict__ out)
{
    const int b = blockIdx.z;
    const float* Ag = g_v + (size_t)b * CC * NN;
    const float* Bg = g_p + (size_t)b * NN * NN;
    const float* Xg = x + (size_t)b * CC * NN;
    float*       Cg = out + (size_t)b * CC * NN;
    const int m0 = blockIdx.y * BM, n0 = blockIdx.x * BN;

    __shared__ __align__(16) float As[BK][BM];
    __shared__ __align__(16) float Bs[BK][BN];

    const int tid = threadIdx.x;
    const int tx = tid & 15, ty = tid >> 4;

    float acc[8][8];
    #pragma unroll
    for (int i = 0; i < 8; i++)
        #pragma unroll
        for (int j = 0; j < 8; j++) acc[i][j] = 0.f;

    const int arow = tid >> 1;
    const int agrp = (tid & 1) * 4;
    const int bkk  = (tid * 4) >> 7;
    const int bnn  = (tid * 4) & 127;

    for (int k0 = 0; k0 < NN; k0 += BK) {
        float4 a = *(const float4*)&Ag[(size_t)(m0 + arow) * NN + k0 + agrp];
        As[agrp + 0][arow] = a.x;
        As[agrp + 1][arow] = a.y;
        As[agrp + 2][arow] = a.z;
        As[agrp + 3][arow] = a.w;
        *(float4*)&Bs[bkk][bnn] =
            *(const float4*)&Bg[(size_t)(k0 + bkk) * NN + n0 + bnn];
        __syncthreads();

        #pragma unroll
        for (int kk = 0; kk < BK; kk++) {
            float av[8], bv[8];
            *(float4*)&av[0] = *(float4*)&As[kk][ty * 8];
            *(float4*)&av[4] = *(float4*)&As[kk][ty * 8 + 4];
            *(float4*)&bv[0] = *(float4*)&Bs[kk][tx * 8];
            *(float4*)&bv[4] = *(float4*)&Bs[kk][tx * 8 + 4];
            #pragma unroll
            for (int i = 0; i < 8; i++)
                #pragma unroll
                for (int j = 0; j < 8; j++)
                    acc[i][j] += av[i] * bv[j];
        }
        __syncthreads();
    }

    const float g = gamma[0];
    #pragma unroll
    for (int i = 0; i < 8; i++) {
        const size_t roff = (size_t)(m0 + ty * 8 + i) * NN + n0 + tx * 8;
        float4 x0 = *(const float4*)&Xg[roff];
        float4 x1 = *(const float4*)&Xg[roff + 4];
        float4 r0, r1;
        r0.x = g * acc[i][0] + x0.x; r0.y = g * acc[i][1] + x0.y;
        r0.z = g * acc[i][2] + x0.z; r0.w = g * acc[i][3] + x0.w;
        r1.x = g * acc[i][4] + x1.x; r1.y = g * acc[i][5] + x1.y;
        r1.z = g * acc[i][6] + x1.z; r1.w = g * acc[i][7] + x1.w;
        *(float4*)&Cg[roff]     = r0;
        *(float4*)&Cg[roff + 4] = r1;
    }
}

// ---------------------------------------------------------------------------
extern "C" void kernel_launch(void* const* d_in, const int* in_sizes, int n_in,
                              void* d_out, int out_size)
{
    const float* x     = (const float*)d_in[0];
    const float* wq    = (const float*)d_in[1];
    const float* bq    = (const float*)d_in[2];
    const float* wk    = (const float*)d_in[3];
    const float* bk    = (const float*)d_in[4];
    const float* wv    = (const float*)d_in[5];
    const float* bv    = (const float*)d_in[6];
    const float* gamma = (const float*)d_in[7];
    float* out = (float*)d_out;

    proj_kernel<<<dim3(NN / BN, CQ / BM, BV), 256>>>(wq, bq, x, CQ, 0);
    proj_kernel<<<dim3(NN / BN, CQ / BM, BV), 256>>>(wk, bk, x, CQ, 1);
    proj_kernel<<<dim3(NN / BN, CC / BM, BV), 256>>>(wv, bv, x, CC, 2);
    scores_kernel<<<dim3(NN / BN, NN / BM, BV), 256>>>();
    softmax_kernel<<<BV * NN, 256>>>();
    av_kernel<<<dim3(NN / BN, CC / BM, BV), 256>>>(x, gamma, out);
}

// round 2
// speedup vs baseline: 2.3494x; 2.3494x over previous
#include <cuda_runtime.h>
#include <cstdint>
#include <cstddef>

// Problem constants
#define BV 4      // batch
#define CC 256    // channels
#define CQ 128    // q/k channels
#define NN 4096   // pixels (64*64)

// Scratch (device globals: allowed)
__device__ float g_q[(size_t)BV * CQ * NN];       // 8 MiB (tf32-rounded)
__device__ float g_k[(size_t)BV * CQ * NN];       // 8 MiB (tf32-rounded)
__device__ float g_v[(size_t)BV * CC * NN];       // 16 MiB (tf32-rounded)
__device__ float g_p[(size_t)BV * NN * NN];       // 256 MiB scores -> attn

#define BM 128
#define BN 128
#define BKP 8     // proj SIMT tile K

// ---------------------------------------------------------------------------
// helpers
// ---------------------------------------------------------------------------
__device__ __forceinline__ float to_tf32(float x) {
    float y;
    asm("cvt.rna.tf32.f32 %0, %1;" : "=f"(y) : "f"(x));
    return y;
}
__device__ __forceinline__ unsigned su32(const void* p) {
    return (unsigned)__cvta_generic_to_shared(p);
}
__device__ __forceinline__ void cp16(unsigned dst, const void* src) {
    asm volatile("cp.async.cg.shared.global [%0], [%1], 16;\n" :: "r"(dst), "l"(src));
}
__device__ __forceinline__ void cp_commit() {
    asm volatile("cp.async.commit_group;\n" ::: "memory");
}
template<int N> __device__ __forceinline__ void cp_wait() {
    asm volatile("cp.async.wait_group %0;\n" :: "n"(N) : "memory");
}
__device__ __forceinline__ void mma_tf32(float c[4],
    uint32_t a0, uint32_t a1, uint32_t a2, uint32_t a3,
    uint32_t b0, uint32_t b1)
{
    asm volatile(
        "mma.sync.aligned.m16n8k8.row.col.f32.tf32.tf32.f32 "
        "{%0,%1,%2,%3}, {%4,%5,%6,%7}, {%8,%9}, {%0,%1,%2,%3};"
        : "+f"(c[0]), "+f"(c[1]), "+f"(c[2]), "+f"(c[3])
        : "r"(a0), "r"(a1), "r"(a2), "r"(a3), "r"(b0), "r"(b1));
}

// ---------------------------------------------------------------------------
// proj: dst[b,m,n] = tf32( sum_k W[m,k] * x[b,k,n] + bias[m] )
// ---------------------------------------------------------------------------
__global__ __launch_bounds__(256) void proj_kernel(
    const float* __restrict__ W, const float* __restrict__ bias,
    const float* __restrict__ x, int M, int sel)
{
    float* dst = (sel == 0) ? g_q : (sel == 1) ? g_k : g_v;
    const int b = blockIdx.z;
    const float* Bg = x + (size_t)b * CC * NN;
    float*       Cg = dst + (size_t)b * M * NN;
    const int m0 = blockIdx.y * BM, n0 = blockIdx.x * BN;

    __shared__ __align__(16) float As[BKP][BM];
    __shared__ __align__(16) float Bs[BKP][BN];

    const int tid = threadIdx.x;
    const int tx = tid & 15, ty = tid >> 4;

    float acc[8][8];
    #pragma unroll
    for (int i = 0; i < 8; i++)
        #pragma unroll
        for (int j = 0; j < 8; j++) acc[i][j] = 0.f;

    const int arow = tid >> 1;
    const int agrp = (tid & 1) * 4;
    const int bkk  = (tid * 4) >> 7;
    const int bnn  = (tid * 4) & 127;

    for (int k0 = 0; k0 < CC; k0 += BKP) {
        float4 a = *(const float4*)&W[(size_t)(m0 + arow) * CC + k0 + agrp];
        As[agrp + 0][arow] = a.x;
        As[agrp + 1][arow] = a.y;
        As[agrp + 2][arow] = a.z;
        As[agrp + 3][arow] = a.w;
        *(float4*)&Bs[bkk][bnn] =
            *(const float4*)&Bg[(size_t)(k0 + bkk) * NN + n0 + bnn];
        __syncthreads();

        #pragma unroll
        for (int kk = 0; kk < BKP; kk++) {
            float av[8], bv[8];
            *(float4*)&av[0] = *(float4*)&As[kk][ty * 8];
            *(float4*)&av[4] = *(float4*)&As[kk][ty * 8 + 4];
            *(float4*)&bv[0] = *(float4*)&Bs[kk][tx * 8];
            *(float4*)&bv[4] = *(float4*)&Bs[kk][tx * 8 + 4];
            #pragma unroll
            for (int i = 0; i < 8; i++)
                #pragma unroll
                for (int j = 0; j < 8; j++)
                    acc[i][j] += av[i] * bv[j];
        }
        __syncthreads();
    }

    #pragma unroll
    for (int i = 0; i < 8; i++) {
        const float bi = bias[m0 + ty * 8 + i];
        float* crow = &Cg[(size_t)(m0 + ty * 8 + i) * NN + n0 + tx * 8];
        float4 r0, r1;
        r0.x = to_tf32(acc[i][0] + bi); r0.y = to_tf32(acc[i][1] + bi);
        r0.z = to_tf32(acc[i][2] + bi); r0.w = to_tf32(acc[i][3] + bi);
        r1.x = to_tf32(acc[i][4] + bi); r1.y = to_tf32(acc[i][5] + bi);
        r1.z = to_tf32(acc[i][6] + bi); r1.w = to_tf32(acc[i][7] + bi);
        *(float4*)&crow[0] = r0;
        *(float4*)&crow[4] = r1;
    }
}

// ---------------------------------------------------------------------------
// scores (tensor-core): S[b,m,n] = sum_d q[d,m] k[d,n]; q,k K-major [128, 4096]
// Block 128x128, 8 warps (2x4), warp tile 64x32, BK=16, 2-stage cp.async.
// ---------------------------------------------------------------------------
#define SKP 136   // padded row stride (floats) for [k][m] tiles
__global__ __launch_bounds__(256) void scores_mma_kernel()
{
    const int b = blockIdx.z;
    const float* Ag = g_q + (size_t)b * CQ * NN;
    const float* Bg = g_k + (size_t)b * CQ * NN;
    float*       Cg = g_p + (size_t)b * NN * NN;
    const int m0 = blockIdx.y * BM, n0 = blockIdx.x * BN;

    __shared__ __align__(16) float As[2][16][SKP];
    __shared__ __align__(16) float Bs[2][16][SKP];

    const int tid  = threadIdx.x;
    const int lane = tid & 31;
    const int gid  = lane >> 2, tg = lane & 3;
    const int wid  = tid >> 5;
    const int wm   = wid >> 2;   // 0..1
    const int wn   = wid & 3;    // 0..3

    float c[4][4][4];
    #pragma unroll
    for (int i = 0; i < 4; i++)
        #pragma unroll
        for (int j = 0; j < 4; j++)
            #pragma unroll
            for (int r = 0; r < 4; r++) c[i][j][r] = 0.f;

    // tile loader: 512 16B-chunks per operand, 2 per thread
    auto load_tile = [&](int k0, int s) {
        #pragma unroll
        for (int i = 0; i < 2; i++) {
            int idx = tid * 2 + i;
            int r = idx >> 5, c4 = (idx & 31) * 4;
            cp16(su32(&As[s][r][c4]), Ag + (size_t)(k0 + r) * NN + m0 + c4);
            cp16(su32(&Bs[s][r][c4]), Bg + (size_t)(k0 + r) * NN + n0 + c4);
        }
        cp_commit();
    };

    load_tile(0, 0);
    const int T = CQ / 16;  // 8
    for (int it = 0; it < T; ++it) {
        if (it + 1 < T) { load_tile((it + 1) * 16, (it + 1) & 1); cp_wait<1>(); }
        else            { cp_wait<0>(); }
        __syncthreads();
        const float (*A)[SKP] = As[it & 1];
        const float (*B)[SKP] = Bs[it & 1];
        #pragma unroll
        for (int kk = 0; kk < 16; kk += 8) {
            uint32_t af[4][4], bf[4][2];
            #pragma unroll
            for (int mi = 0; mi < 4; mi++) {
                int m = wm * 64 + mi * 16 + gid;
                af[mi][0] = __float_as_uint(A[kk + tg    ][m]);
                af[mi][1] = __float_as_uint(A[kk + tg    ][m + 8]);
                af[mi][2] = __float_as_uint(A[kk + tg + 4][m]);
                af[mi][3] = __float_as_uint(A[kk + tg + 4][m + 8]);
            }
            #pragma unroll
            for (int ni = 0; ni < 4; ni++) {
                int n = wn * 32 + ni * 8 + gid;
                bf[ni][0] = __float_as_uint(B[kk + tg    ][n]);
                bf[ni][1] = __float_as_uint(B[kk + tg + 4][n]);
            }
            #pragma unroll
            for (int mi = 0; mi < 4; mi++)
                #pragma unroll
                for (int ni = 0; ni < 4; ni++)
                    mma_tf32(c[mi][ni], af[mi][0], af[mi][1], af[mi][2], af[mi][3],
                             bf[ni][0], bf[ni][1]);
        }
        __syncthreads();
    }

    #pragma unroll
    for (int mi = 0; mi < 4; mi++) {
        #pragma unroll
        for (int ni = 0; ni < 4; ni++) {
            int row = m0 + wm * 64 + mi * 16 + gid;
            int col = n0 + wn * 32 + ni * 8 + tg * 2;
            float2 v0 = {c[mi][ni][0], c[mi][ni][1]};
            float2 v1 = {c[mi][ni][2], c[mi][ni][3]};
            *(float2*)&Cg[(size_t)row * NN + col]       = v0;
            *(float2*)&Cg[(size_t)(row + 8) * NN + col] = v1;
        }
    }
}

// ---------------------------------------------------------------------------
// softmax over last axis, in place, writes tf32-rounded weights
// ---------------------------------------------------------------------------
__global__ __launch_bounds__(256) void softmax_kernel()
{
    const size_t row = blockIdx.x;
    float* p = g_p + row * (size_t)NN;
    const int tid = threadIdx.x;
    const int lane = tid & 31, wid = tid >> 5;

    __shared__ float red[32];

    float4 v[4];
    float mx = -1e30f;
    #pragma unroll
    for (int i = 0; i < 4; i++) {
        v[i] = *(const float4*)&p[i * 1024 + tid * 4];
        mx = fmaxf(mx, fmaxf(fmaxf(v[i].x, v[i].y), fmaxf(v[i].z, v[i].w)));
    }
    #pragma unroll
    for (int o = 16; o; o >>= 1) mx = fmaxf(mx, __shfl_xor_sync(0xffffffffu, mx, o));
    if (lane == 0) red[wid] = mx;
    __syncthreads();
    if (tid == 0) {
        float m = red[0];
        #pragma unroll
        for (int i = 1; i < 8; i++) m = fmaxf(m, red[i]);
        red[0] = m;
    }
    __syncthreads();
    mx = red[0];
    __syncthreads();

    float s = 0.f;
    #pragma unroll
    for (int i = 0; i < 4; i++) {
        v[i].x = __expf(v[i].x - mx);
        v[i].y = __expf(v[i].y - mx);
        v[i].z = __expf(v[i].z - mx);
        v[i].w = __expf(v[i].w - mx);
        s += v[i].x + v[i].y + v[i].z + v[i].w;
    }
    #pragma unroll
    for (int o = 16; o; o >>= 1) s += __shfl_xor_sync(0xffffffffu, s, o);
    if (lane == 0) red[wid] = s;
    __syncthreads();
    if (tid == 0) {
        float t = 0.f;
        #pragma unroll
        for (int i = 0; i < 8; i++) t += red[i];
        red[0] = t;
    }
    __syncthreads();
    const float inv = 1.0f / red[0];

    #pragma unroll
    for (int i = 0; i < 4; i++) {
        v[i].x = to_tf32(v[i].x * inv); v[i].y = to_tf32(v[i].y * inv);
        v[i].z = to_tf32(v[i].z * inv); v[i].w = to_tf32(v[i].w * inv);
        *(float4*)&p[i * 1024 + tid * 4] = v[i];
    }
}

// ---------------------------------------------------------------------------
// av (tensor-core): out[b,c,j] = gamma * sum_i v[c,i] P[i,j] + x[b,c,j]
// A = v [256, 4096] row-major (k contiguous) -> SMEM [m][k] pad 20
// B = P [4096, 4096] (n contiguous) -> SMEM [k][n] pad 136
// ---------------------------------------------------------------------------
#define AKP 20
__global__ __launch_bounds__(256) void av_mma_kernel(
    const float* __restrict__ x, const float* __restrict__ gamma,
    float* __restrict__ out)
{
    const int b = blockIdx.z;
    const float* Ag = g_v + (size_t)b * CC * NN;
    const float* Bg = g_p + (size_t)b * NN * NN;
    const float* Xg = x + (size_t)b * CC * NN;
    float*       Cg = out + (size_t)b * CC * NN;
    const int m0 = blockIdx.y * BM, n0 = blockIdx.x * BN;

    __shared__ __align__(16) float Am[2][128][AKP];
    __shared__ __align__(16) float Bs[2][16][SKP];

    const int tid  = threadIdx.x;
    const int lane = tid & 31;
    const int gid  = lane >> 2, tg = lane & 3;
    const int wid  = tid >> 5;
    const int wm   = wid >> 2;
    const int wn   = wid & 3;

    float c[4][4][4];
    #pragma unroll
    for (int i = 0; i < 4; i++)
        #pragma unroll
        for (int j = 0; j < 4; j++)
            #pragma unroll
            for (int r = 0; r < 4; r++) c[i][j][r] = 0.f;

    auto load_tile = [&](int k0, int s) {
        #pragma unroll
        for (int i = 0; i < 2; i++) {
            int idx = tid * 2 + i;
            // A: [m][k] — m = idx>>2 (0..127), 4-float chunk q = idx&3
            int am = idx >> 2, aq = (idx & 3) * 4;
            cp16(su32(&Am[s][am][aq]), Ag + (size_t)(m0 + am) * NN + k0 + aq);
            // B: [k][n]
            int r = idx >> 5, c4 = (idx & 31) * 4;
            cp16(su32(&Bs[s][r][c4]), Bg + (size_t)(k0 + r) * NN + n0 + c4);
        }
        cp_commit();
    };

    load_tile(0, 0);
    const int T = NN / 16;  // 256
    for (int it = 0; it < T; ++it) {
        if (it + 1 < T) { load_tile((it + 1) * 16, (it + 1) & 1); cp_wait<1>(); }
        else            { cp_wait<0>(); }
        __syncthreads();
        const float (*A)[AKP] = Am[it & 1];
        const float (*B)[SKP] = Bs[it & 1];
        #pragma unroll
        for (int kk = 0; kk < 16; kk += 8) {
            uint32_t af[4][4], bf[4][2];
            #pragma unroll
            for (int mi = 0; mi < 4; mi++) {
                int m = wm * 64 + mi * 16 + gid;
                af[mi][0] = __float_as_uint(A[m    ][kk + tg]);
                af[mi][1] = __float_as_uint(A[m + 8][kk + tg]);
                af[mi][2] = __float_as_uint(A[m    ][kk + tg + 4]);
                af[mi][3] = __float_as_uint(A[m + 8][kk + tg + 4]);
            }
            #pragma unroll
            for (int ni = 0; ni < 4; ni++) {
                int n = wn * 32 + ni * 8 + gid;
                bf[ni][0] = __float_as_uint(B[kk + tg    ][n]);
                bf[ni][1] = __float_as_uint(B[kk + tg + 4][n]);
            }
            #pragma unroll
            for (int mi = 0; mi < 4; mi++)
                #pragma unroll
                for (int ni = 0; ni < 4; ni++)
                    mma_tf32(c[mi][ni], af[mi][0], af[mi][1], af[mi][2], af[mi][3],
                             bf[ni][0], bf[ni][1]);
        }
        __syncthreads();
    }

    const float g = gamma[0];
    #pragma unroll
    for (int mi = 0; mi < 4; mi++) {
        #pragma unroll
        for (int ni = 0; ni < 4; ni++) {
            int row = m0 + wm * 64 + mi * 16 + gid;
            int col = n0 + wn * 32 + ni * 8 + tg * 2;
            size_t o0 = (size_t)row * NN + col;
            size_t o1 = (size_t)(row + 8) * NN + col;
            float2 x0 = *(const float2*)&Xg[o0];
            float2 x1 = *(const float2*)&Xg[o1];
            float2 r0 = {g * c[mi][ni][0] + x0.x, g * c[mi][ni][1] + x0.y};
            float2 r1 = {g * c[mi][ni][2] + x1.x, g * c[mi][ni][3] + x1.y};
            *(float2*)&Cg[o0] = r0;
            *(float2*)&Cg[o1] = r1;
        }
    }
}

// ---------------------------------------------------------------------------
extern "C" void kernel_launch(void* const* d_in, const int* in_sizes, int n_in,
                              void* d_out, int out_size)
{
    const float* x     = (const float*)d_in[0];
    const float* wq    = (const float*)d_in[1];
    const float* bq    = (const float*)d_in[2];
    const float* wk    = (const float*)d_in[3];
    const float* bk    = (const float*)d_in[4];
    const float* wv    = (const float*)d_in[5];
    const float* bv    = (const float*)d_in[6];
    const float* gamma = (const float*)d_in[7];
    float* out = (float*)d_out;

    proj_kernel<<<dim3(NN / BN, CQ / BM, BV), 256>>>(wq, bq, x, CQ, 0);
    proj_kernel<<<dim3(NN / BN, CQ / BM, BV), 256>>>(wk, bk, x, CQ, 1);
    proj_kernel<<<dim3(NN / BN, CC / BM, BV), 256>>>(wv, bv, x, CC, 2);
    scores_mma_kernel<<<dim3(NN / BN, NN / BM, BV), 256>>>();
    softmax_kernel<<<BV * NN, 256>>>();
    av_mma_kernel<<<dim3(NN / BN, CC / BM, BV), 256>>>(x, gamma, out);
}

// round 7
// speedup vs baseline: 3.5029x; 1.4910x over previous
#include <cuda_runtime.h>
#include <cuda_bf16.h>
#include <cstdint>
#include <cstddef>

// Problem constants
#define BV 4      // batch
#define CC 256    // channels
#define CQ 128    // q/k channels
#define NN 4096   // pixels (64*64)

// Scratch (device globals)
__device__ float g_q[(size_t)BV * CQ * NN];            // tf32-rounded
__device__ float g_k[(size_t)BV * CQ * NN];            // tf32-rounded
__device__ float g_v[(size_t)BV * CC * NN];            // fp32
__device__ float g_z[(size_t)BV * NN];                 // exp row sums
__device__ __nv_bfloat16 g_vb[(size_t)BV * CC * NN];   // v / Z  (bf16)
__device__ __nv_bfloat16 g_pb[(size_t)BV * NN * NN];   // exp(S) (bf16), 128 MiB

#define BM 128
#define BN 128
#define BKP 8     // proj SIMT tile K

// ---------------------------------------------------------------------------
// helpers
// ---------------------------------------------------------------------------
__device__ __forceinline__ float to_tf32(float x) {
    float y;
    asm("cvt.rna.tf32.f32 %0, %1;" : "=f"(y) : "f"(x));
    return y;
}
__device__ __forceinline__ unsigned su32(const void* p) {
    return (unsigned)__cvta_generic_to_shared(p);
}
__device__ __forceinline__ void cp16(unsigned dst, const void* src) {
    asm volatile("cp.async.cg.shared.global [%0], [%1], 16;\n" :: "r"(dst), "l"(src));
}
__device__ __forceinline__ void cp_commit() {
    asm volatile("cp.async.commit_group;\n" ::: "memory");
}
template<int N> __device__ __forceinline__ void cp_wait() {
    asm volatile("cp.async.wait_group %0;\n" :: "n"(N) : "memory");
}
__device__ __forceinline__ void mma_tf32(float c[4],
    uint32_t a0, uint32_t a1, uint32_t a2, uint32_t a3,
    uint32_t b0, uint32_t b1)
{
    asm volatile(
        "mma.sync.aligned.m16n8k8.row.col.f32.tf32.tf32.f32 "
        "{%0,%1,%2,%3}, {%4,%5,%6,%7}, {%8,%9}, {%0,%1,%2,%3};"
        : "+f"(c[0]), "+f"(c[1]), "+f"(c[2]), "+f"(c[3])
        : "r"(a0), "r"(a1), "r"(a2), "r"(a3), "r"(b0), "r"(b1));
}
__device__ __forceinline__ void mma_bf16(float c[4],
    uint32_t a0, uint32_t a1, uint32_t a2, uint32_t a3,
    uint32_t b0, uint32_t b1)
{
    asm volatile(
        "mma.sync.aligned.m16n8k16.row.col.f32.bf16.bf16.f32 "
        "{%0,%1,%2,%3}, {%4,%5,%6,%7}, {%8,%9}, {%0,%1,%2,%3};"
        : "+f"(c[0]), "+f"(c[1]), "+f"(c[2]), "+f"(c[3])
        : "r"(a0), "r"(a1), "r"(a2), "r"(a3), "r"(b0), "r"(b1));
}
__device__ __forceinline__ void ldsm_x4(uint32_t& r0, uint32_t& r1,
                                        uint32_t& r2, uint32_t& r3, unsigned a)
{
    asm volatile("ldmatrix.sync.aligned.m8n8.x4.shared.b16 {%0,%1,%2,%3}, [%4];"
        : "=r"(r0), "=r"(r1), "=r"(r2), "=r"(r3) : "r"(a));
}
__device__ __forceinline__ void ldsm_x4_t(uint32_t& r0, uint32_t& r1,
                                          uint32_t& r2, uint32_t& r3, unsigned a)
{
    asm volatile("ldmatrix.sync.aligned.m8n8.x4.trans.shared.b16 {%0,%1,%2,%3}, [%4];"
        : "=r"(r0), "=r"(r1), "=r"(r2), "=r"(r3) : "r"(a));
}

// ---------------------------------------------------------------------------
// proj: dst[b,m,n] = tf32( sum_k W[m,k] * x[b,k,n] + bias[m] )
// ---------------------------------------------------------------------------
__global__ __launch_bounds__(256) void proj_kernel(
    const float* __restrict__ W, const float* __restrict__ bias,
    const float* __restrict__ x, int M, int sel)
{
    float* dst = (sel == 0) ? g_q : (sel == 1) ? g_k : g_v;
    const int b = blockIdx.z;
    const float* Bg = x + (size_t)b * CC * NN;
    float*       Cg = dst + (size_t)b * M * NN;
    const int m0 = blockIdx.y * BM, n0 = blockIdx.x * BN;

    __shared__ __align__(16) float As[BKP][BM];
    __shared__ __align__(16) float Bs[BKP][BN];

    const int tid = threadIdx.x;
    const int tx = tid & 15, ty = tid >> 4;

    float acc[8][8];
    #pragma unroll
    for (int i = 0; i < 8; i++)
        #pragma unroll
        for (int j = 0; j < 8; j++) acc[i][j] = 0.f;

    const int arow = tid >> 1;
    const int agrp = (tid & 1) * 4;
    const int bkk  = (tid * 4) >> 7;
    const int bnn  = (tid * 4) & 127;

    for (int k0 = 0; k0 < CC; k0 += BKP) {
        float4 a = *(const float4*)&W[(size_t)(m0 + arow) * CC + k0 + agrp];
        As[agrp + 0][arow] = a.x;
        As[agrp + 1][arow] = a.y;
        As[agrp + 2][arow] = a.z;
        As[agrp + 3][arow] = a.w;
        *(float4*)&Bs[bkk][bnn] =
            *(const float4*)&Bg[(size_t)(k0 + bkk) * NN + n0 + bnn];
        __syncthreads();

        #pragma unroll
        for (int kk = 0; kk < BKP; kk++) {
            float av[8], bv[8];
            *(float4*)&av[0] = *(float4*)&As[kk][ty * 8];
            *(float4*)&av[4] = *(float4*)&As[kk][ty * 8 + 4];
            *(float4*)&bv[0] = *(float4*)&Bs[kk][tx * 8];
            *(float4*)&bv[4] = *(float4*)&Bs[kk][tx * 8 + 4];
            #pragma unroll
            for (int i = 0; i < 8; i++)
                #pragma unroll
                for (int j = 0; j < 8; j++)
                    acc[i][j] += av[i] * bv[j];
        }
        __syncthreads();
    }

    #pragma unroll
    for (int i = 0; i < 8; i++) {
        const float bi = bias[m0 + ty * 8 + i];
        float* crow = &Cg[(size_t)(m0 + ty * 8 + i) * NN + n0 + tx * 8];
        float4 r0, r1;
        r0.x = to_tf32(acc[i][0] + bi); r0.y = to_tf32(acc[i][1] + bi);
        r0.z = to_tf32(acc[i][2] + bi); r0.w = to_tf32(acc[i][3] + bi);
        r1.x = to_tf32(acc[i][4] + bi); r1.y = to_tf32(acc[i][5] + bi);
        r1.z = to_tf32(acc[i][6] + bi); r1.w = to_tf32(acc[i][7] + bi);
        *(float4*)&crow[0] = r0;
        *(float4*)&crow[4] = r1;
    }
}

// ---------------------------------------------------------------------------
// zero g_z
// ---------------------------------------------------------------------------
__global__ void zero_z_kernel() {
    int i = blockIdx.x * 256 + threadIdx.x;
    if (i < BV * NN) g_z[i] = 0.f;
}

// ---------------------------------------------------------------------------
// scores (tf32 mma): S = QtK; epilogue writes bf16 exp(S) + atomic row sums
// ---------------------------------------------------------------------------
#define SKP 136
__global__ __launch_bounds__(256) void scores_mma_kernel()
{
    const int b = blockIdx.z;
    const float* Ag = g_q + (size_t)b * CQ * NN;
    const float* Bg = g_k + (size_t)b * CQ * NN;
    __nv_bfloat16* Pg = g_pb + (size_t)b * NN * NN;
    const int m0 = blockIdx.y * BM, n0 = blockIdx.x * BN;

    __shared__ __align__(16) float As[2][16][SKP];
    __shared__ __align__(16) float Bs[2][16][SKP];

    const int tid  = threadIdx.x;
    const int lane = tid & 31;
    const int gid  = lane >> 2, tg = lane & 3;
    const int wid  = tid >> 5;
    const int wm   = wid >> 2;   // 0..1
    const int wn   = wid & 3;    // 0..3

    float c[4][4][4];
    #pragma unroll
    for (int i = 0; i < 4; i++)
        #pragma unroll
        for (int j = 0; j < 4; j++)
            #pragma unroll
            for (int r = 0; r < 4; r++) c[i][j][r] = 0.f;

    auto load_tile = [&](int k0, int s) {
        #pragma unroll
        for (int i = 0; i < 2; i++) {
            int idx = tid * 2 + i;
            int r = idx >> 5, c4 = (idx & 31) * 4;
            cp16(su32(&As[s][r][c4]), Ag + (size_t)(k0 + r) * NN + m0 + c4);
            cp16(su32(&Bs[s][r][c4]), Bg + (size_t)(k0 + r) * NN + n0 + c4);
        }
        cp_commit();
    };

    const int T = CQ / 16;  // 8
    load_tile(0, 0);
    for (int it = 0; it < T; ++it) {
        cp_wait<0>();
        __syncthreads();
        if (it + 1 < T) load_tile((it + 1) * 16, (it + 1) & 1);
        const float (*A)[SKP] = As[it & 1];
        const float (*B)[SKP] = Bs[it & 1];
        #pragma unroll
        for (int kk = 0; kk < 16; kk += 8) {
            uint32_t af[4][4], bf[4][2];
            #pragma unroll
            for (int mi = 0; mi < 4; mi++) {
                int m = wm * 64 + mi * 16 + gid;
                af[mi][0] = __float_as_uint(A[kk + tg    ][m]);
                af[mi][1] = __float_as_uint(A[kk + tg    ][m + 8]);
                af[mi][2] = __float_as_uint(A[kk + tg + 4][m]);
                af[mi][3] = __float_as_uint(A[kk + tg + 4][m + 8]);
            }
            #pragma unroll
            for (int ni = 0; ni < 4; ni++) {
                int n = wn * 32 + ni * 8 + gid;
                bf[ni][0] = __float_as_uint(B[kk + tg    ][n]);
                bf[ni][1] = __float_as_uint(B[kk + tg + 4][n]);
            }
            #pragma unroll
            for (int mi = 0; mi < 4; mi++)
                #pragma unroll
                for (int ni = 0; ni < 4; ni++)
                    mma_tf32(c[mi][ni], af[mi][0], af[mi][1], af[mi][2], af[mi][3],
                             bf[ni][0], bf[ni][1]);
        }
    }

    // epilogue: exp -> bf16 store, warp-reduced row sums -> atomicAdd
    #pragma unroll
    for (int mi = 0; mi < 4; mi++) {
        const int row = m0 + wm * 64 + mi * 16 + gid;
        float rs0 = 0.f, rs1 = 0.f;
        #pragma unroll
        for (int ni = 0; ni < 4; ni++) {
            const int col = n0 + wn * 32 + ni * 8 + tg * 2;
            float e00 = __expf(c[mi][ni][0]);
            float e01 = __expf(c[mi][ni][1]);
            float e10 = __expf(c[mi][ni][2]);
            float e11 = __expf(c[mi][ni][3]);
            __nv_bfloat162 p0 = __float22bfloat162_rn(make_float2(e00, e01));
            __nv_bfloat162 p1 = __float22bfloat162_rn(make_float2(e10, e11));
            *(__nv_bfloat162*)&Pg[(size_t)row * NN + col]       = p0;
            *(__nv_bfloat162*)&Pg[(size_t)(row + 8) * NN + col] = p1;
            rs0 += __bfloat162float(p0.x) + __bfloat162float(p0.y);
            rs1 += __bfloat162float(p1.x) + __bfloat162float(p1.y);
        }
        rs0 += __shfl_xor_sync(0xffffffffu, rs0, 1);
        rs0 += __shfl_xor_sync(0xffffffffu, rs0, 2);
        rs1 += __shfl_xor_sync(0xffffffffu, rs1, 1);
        rs1 += __shfl_xor_sync(0xffffffffu, rs1, 2);
        if (tg == 0) {
            atomicAdd(&g_z[(size_t)b * NN + row],     rs0);
            atomicAdd(&g_z[(size_t)b * NN + row + 8], rs1);
        }
    }
}

// ---------------------------------------------------------------------------
// vscale: g_vb[b,c,i] = bf16( g_v[b,c,i] / Z[b,i] )
// ---------------------------------------------------------------------------
__global__ __launch_bounds__(256) void vscale_kernel() {
    size_t t = (size_t)blockIdx.x * 256 + threadIdx.x;
    size_t base = t * 4;  // over BV*CC*NN
    float4 v = *(const float4*)&g_v[base];
    size_t i = base % NN;
    size_t b = base / ((size_t)CC * NN);
    const float* z = &g_z[b * NN + i];
    __nv_bfloat162 o0 = __float22bfloat162_rn(
        make_float2(__fdividef(v.x, z[0]), __fdividef(v.y, z[1])));
    __nv_bfloat162 o1 = __float22bfloat162_rn(
        make_float2(__fdividef(v.z, z[2]), __fdividef(v.w, z[3])));
    *(__nv_bfloat162*)&g_vb[base]     = o0;
    *(__nv_bfloat162*)&g_vb[base + 2] = o1;
}

// ---------------------------------------------------------------------------
// av (bf16 mma): out[b,c,j] = gamma * sum_i vb[c,i] * pb[i,j] + x[b,c,j]
// A = g_vb [CC][NN] row-major; B = g_pb [NN][NN] (j contiguous)
// Block 128x128, BK=32, 2 stages, ldmatrix feeds.
// ---------------------------------------------------------------------------
#define A_PAD 40    // bf16 elems per A smem row (80 B, conflict-free ldmatrix)
#define B_PAD 136   // bf16 elems per B smem row (272 B, conflict-free ldmatrix)
__global__ __launch_bounds__(256) void av_bf16_kernel(
    const float* __restrict__ x, const float* __restrict__ gamma,
    float* __restrict__ out)
{
    const int b = blockIdx.z;
    const __nv_bfloat16* Ag = g_vb + (size_t)b * CC * NN;
    const __nv_bfloat16* Bg = g_pb + (size_t)b * NN * NN;
    const float* Xg = x + (size_t)b * CC * NN;
    float*       Cg = out + (size_t)b * CC * NN;
    const int m0 = blockIdx.y * BM, n0 = blockIdx.x * BN;

    __shared__ __align__(16) __nv_bfloat16 Asm[2][128][A_PAD];
    __shared__ __align__(16) __nv_bfloat16 Bsm[2][32][B_PAD];

    const int tid  = threadIdx.x;
    const int lane = tid & 31;
    const int gid  = lane >> 2, tg = lane & 3;
    const int wid  = tid >> 5;
    const int wm   = wid >> 2;   // 0..1
    const int wn   = wid & 3;    // 0..3

    const int fr_row = (lane & 7) + ((lane >> 3) & 1) * 8;  // 0..15
    const int fr_hi  = ((lane >> 4) & 1) * 8;               // 0 or 8

    float c[4][4][4];
    #pragma unroll
    for (int i = 0; i < 4; i++)
        #pragma unroll
        for (int j = 0; j < 4; j++)
            #pragma unroll
            for (int r = 0; r < 4; r++) c[i][j][r] = 0.f;

    auto load_tile = [&](int k0, int s) {
        #pragma unroll
        for (int i = 0; i < 2; i++) {
            int idx = tid * 2 + i;            // 0..511
            int am = idx >> 2, aq = (idx & 3) * 8;
            cp16(su32(&Asm[s][am][aq]), Ag + (size_t)(m0 + am) * NN + k0 + aq);
            int br = idx >> 4, bc = (idx & 15) * 8;
            cp16(su32(&Bsm[s][br][bc]), Bg + (size_t)(k0 + br) * NN + n0 + bc);
        }
        cp_commit();
    };

    const int T = NN / 32;  // 128
    load_tile(0, 0);
    for (int it = 0; it < T; ++it) {
        cp_wait<0>();
        __syncthreads();
        if (it + 1 < T) load_tile((it + 1) * 32, (it + 1) & 1);
        const __nv_bfloat16 (*A)[A_PAD] = Asm[it & 1];
        const __nv_bfloat16 (*B)[B_PAD] = Bsm[it & 1];
        #pragma unroll
        for (int kk = 0; kk < 32; kk += 16) {
            uint32_t af[4][4], bfg[4][2];
            #pragma unroll
            for (int mi = 0; mi < 4; mi++) {
                unsigned ad = su32(&A[wm * 64 + mi * 16 + fr_row][kk + fr_hi]);
                ldsm_x4(af[mi][0], af[mi][1], af[mi][2], af[mi][3], ad);
            }
            #pragma unroll
            for (int nj = 0; nj < 2; nj++) {
                unsigned bd = su32(&B[kk + fr_row][wn * 32 + nj * 16 + fr_hi]);
                ldsm_x4_t(bfg[2 * nj][0], bfg[2 * nj][1],
                          bfg[2 * nj + 1][0], bfg[2 * nj + 1][1], bd);
            }
            #pragma unroll
            for (int mi = 0; mi < 4; mi++)
                #pragma unroll
                for (int ni = 0; ni < 4; ni++)
                    mma_bf16(c[mi][ni], af[mi][0], af[mi][1], af[mi][2], af[mi][3],
                             bfg[ni][0], bfg[ni][1]);
        }
    }

    const float g = gamma[0];
    #pragma unroll
    for (int mi = 0; mi < 4; mi++) {
        #pragma unroll
        for (int ni = 0; ni < 4; ni++) {
            int row = m0 + wm * 64 + mi * 16 + gid;
            int col = n0 + wn * 32 + ni * 8 + tg * 2;
            size_t o0 = (size_t)row * NN + col;
            size_t o1 = (size_t)(row + 8) * NN + col;
            float2 x0 = *(const float2*)&Xg[o0];
            float2 x1 = *(const float2*)&Xg[o1];
            float2 r0 = {g * c[mi][ni][0] + x0.x, g * c[mi][ni][1] + x0.y};
            float2 r1 = {g * c[mi][ni][2] + x1.x, g * c[mi][ni][3] + x1.y};
            *(float2*)&Cg[o0] = r0;
            *(float2*)&Cg[o1] = r1;
        }
    }
}

// ---------------------------------------------------------------------------
extern "C" void kernel_launch(void* const* d_in, const int* in_sizes, int n_in,
                              void* d_out, int out_size)
{
    const float* x     = (const float*)d_in[0];
    const float* wq    = (const float*)d_in[1];
    const float* bq    = (const float*)d_in[2];
    const float* wk    = (const float*)d_in[3];
    const float* bk    = (const float*)d_in[4];
    const float* wv    = (const float*)d_in[5];
    const float* bv    = (const float*)d_in[6];
    const float* gamma = (const float*)d_in[7];
    float* out = (float*)d_out;

    proj_kernel<<<dim3(NN / BN, CQ / BM, BV), 256>>>(wq, bq, x, CQ, 0);
    proj_kernel<<<dim3(NN / BN, CQ / BM, BV), 256>>>(wk, bk, x, CQ, 1);
    proj_kernel<<<dim3(NN / BN, CC / BM, BV), 256>>>(wv, bv, x, CC, 2);
    zero_z_kernel<<<(BV * NN + 255) / 256, 256>>>();
    scores_mma_kernel<<<dim3(NN / BN, NN / BM, BV), 256>>>();
    vscale_kernel<<<(BV * CC * NN / 4 + 255) / 256, 256>>>();
    av_bf16_kernel<<<dim3(NN / BN, CC / BM, BV), 256>>>(x, gamma, out);
}

// round 10
// speedup vs baseline: 4.3985x; 1.2557x over previous
#include <cuda_runtime.h>
#include <cuda_bf16.h>
#include <cstdint>
#include <cstddef>

// Problem constants
#define BV 4      // batch
#define CC 256    // channels
#define CQ 128    // q/k channels
#define NN 4096   // pixels (64*64)

// Scratch (device globals)
__device__ float g_q[(size_t)BV * CQ * NN];            // tf32-rounded
__device__ float g_k[(size_t)BV * CQ * NN];            // tf32-rounded
__device__ float g_v[(size_t)BV * CC * NN];            // fp32 (tf32-accurate)
__device__ float g_z[(size_t)BV * NN];                 // exp row sums
__device__ __nv_bfloat16 g_vb[(size_t)BV * CC * NN];   // v / Z  (bf16)
__device__ __nv_bfloat16 g_pb[(size_t)BV * NN * NN];   // exp(S) (bf16), 128 MiB

#define BM 128
#define BN 128

// ---------------------------------------------------------------------------
// helpers
// ---------------------------------------------------------------------------
__device__ __forceinline__ float to_tf32(float x) {
    float y;
    asm("cvt.rna.tf32.f32 %0, %1;" : "=f"(y) : "f"(x));
    return y;
}
__device__ __forceinline__ uint32_t tf32_bits(float x) {
    return __float_as_uint(to_tf32(x));
}
__device__ __forceinline__ unsigned su32(const void* p) {
    return (unsigned)__cvta_generic_to_shared(p);
}
__device__ __forceinline__ void cp16(unsigned dst, const void* src) {
    asm volatile("cp.async.cg.shared.global [%0], [%1], 16;\n" :: "r"(dst), "l"(src));
}
__device__ __forceinline__ void cp_commit() {
    asm volatile("cp.async.commit_group;\n" ::: "memory");
}
template<int N> __device__ __forceinline__ void cp_wait() {
    asm volatile("cp.async.wait_group %0;\n" :: "n"(N) : "memory");
}
__device__ __forceinline__ void mma_tf32(float c[4],
    uint32_t a0, uint32_t a1, uint32_t a2, uint32_t a3,
    uint32_t b0, uint32_t b1)
{
    asm volatile(
        "mma.sync.aligned.m16n8k8.row.col.f32.tf32.tf32.f32 "
        "{%0,%1,%2,%3}, {%4,%5,%6,%7}, {%8,%9}, {%0,%1,%2,%3};"
        : "+f"(c[0]), "+f"(c[1]), "+f"(c[2]), "+f"(c[3])
        : "r"(a0), "r"(a1), "r"(a2), "r"(a3), "r"(b0), "r"(b1));
}
__device__ __forceinline__ void mma_bf16(float c[4],
    uint32_t a0, uint32_t a1, uint32_t a2, uint32_t a3,
    uint32_t b0, uint32_t b1)
{
    asm volatile(
        "mma.sync.aligned.m16n8k16.row.col.f32.bf16.bf16.f32 "
        "{%0,%1,%2,%3}, {%4,%5,%6,%7}, {%8,%9}, {%0,%1,%2,%3};"
        : "+f"(c[0]), "+f"(c[1]), "+f"(c[2]), "+f"(c[3])
        : "r"(a0), "r"(a1), "r"(a2), "r"(a3), "r"(b0), "r"(b1));
}
__device__ __forceinline__ void ldsm_x4(uint32_t& r0, uint32_t& r1,
                                        uint32_t& r2, uint32_t& r3, unsigned a)
{
    asm volatile("ldmatrix.sync.aligned.m8n8.x4.shared.b16 {%0,%1,%2,%3}, [%4];"
        : "=r"(r0), "=r"(r1), "=r"(r2), "=r"(r3) : "r"(a));
}
__device__ __forceinline__ void ldsm_x4_t(uint32_t& r0, uint32_t& r1,
                                          uint32_t& r2, uint32_t& r3, unsigned a)
{
    asm volatile("ldmatrix.sync.aligned.m8n8.x4.trans.shared.b16 {%0,%1,%2,%3}, [%4];"
        : "=r"(r0), "=r"(r1), "=r"(r2), "=r"(r3) : "r"(a));
}

// ---------------------------------------------------------------------------
// fused projection (tf32 mma): one kernel for q, k, v.
//   blockIdx.y: 0 -> q, 1 -> k, 2 -> v[0:128), 3 -> v[128:256)
//   C[128,128] = Wsel[128, 256] x x[256(k), 128(n)] + bias; q/k tf32-rounded.
// A smem [m][k] pad 20, B smem [k][n] pad 136, BK=16, 2-stage cp.async.
// ---------------------------------------------------------------------------
#define PAK 20
#define SKP 136
__global__ __launch_bounds__(256) void proj_mma_kernel(
    const float* __restrict__ wq, const float* __restrict__ bq,
    const float* __restrict__ wk, const float* __restrict__ bk,
    const float* __restrict__ wv, const float* __restrict__ bv,
    const float* __restrict__ x)
{
    const int b = blockIdx.z;
    const int yb = blockIdx.y;

    const float* W;
    const float* bias;
    float* dst;
    bool rnd;
    if (yb == 0)      { W = wq;             bias = bq;       dst = g_q + (size_t)b * CQ * NN;            rnd = true; }
    else if (yb == 1) { W = wk;             bias = bk;       dst = g_k + (size_t)b * CQ * NN;            rnd = true; }
    else if (yb == 2) { W = wv;             bias = bv;       dst = g_v + (size_t)b * CC * NN;            rnd = false; }
    else              { W = wv + 128 * CC;  bias = bv + 128; dst = g_v + (size_t)b * CC * NN + 128 * NN; rnd = false; }

    const float* Bg = x + (size_t)b * CC * NN;
    const int n0 = blockIdx.x * BN;

    __shared__ __align__(16) float As[2][128][PAK];
    __shared__ __align__(16) float Bs[2][16][SKP];

    const int tid  = threadIdx.x;
    const int lane = tid & 31;
    const int gid  = lane >> 2, tg = lane & 3;
    const int wid  = tid >> 5;
    const int wm   = wid >> 2;   // 0..1
    const int wn   = wid & 3;    // 0..3

    float c[4][4][4];
    #pragma unroll
    for (int i = 0; i < 4; i++)
        #pragma unroll
        for (int j = 0; j < 4; j++)
            #pragma unroll
            for (int r = 0; r < 4; r++) c[i][j][r] = 0.f;

    auto load_tile = [&](int k0, int s) {
        #pragma unroll
        for (int i = 0; i < 4; i++) {
            int idx = tid * 4 + i;           // 0..1023
            if (idx < 512) {                  // A: 128 m x 16 k
                int am = idx >> 2, aq = (idx & 3) * 4;
                cp16(su32(&As[s][am][aq]), W + (size_t)am * CC + k0 + aq);
            } else {                          // B: 16 k x 128 n
                int j = idx - 512;
                int br = j >> 5, bc = (j & 31) * 4;
                cp16(su32(&Bs[s][br][bc]), Bg + (size_t)(k0 + br) * NN + n0 + bc);
            }
        }
        cp_commit();
    };

    const int T = CC / 16;   // 16
    load_tile(0, 0);
    for (int it = 0; it < T; ++it) {
        cp_wait<0>();
        __syncthreads();
        if (it + 1 < T) load_tile((it + 1) * 16, (it + 1) & 1);
        const float (*A)[PAK] = As[it & 1];
        const float (*B)[SKP] = Bs[it & 1];
        #pragma unroll
        for (int kk = 0; kk < 16; kk += 8) {
            uint32_t af[4][4], bf[4][2];
            #pragma unroll
            for (int mi = 0; mi < 4; mi++) {
                int m = wm * 64 + mi * 16 + gid;
                af[mi][0] = tf32_bits(A[m    ][kk + tg]);
                af[mi][1] = tf32_bits(A[m + 8][kk + tg]);
                af[mi][2] = tf32_bits(A[m    ][kk + tg + 4]);
                af[mi][3] = tf32_bits(A[m + 8][kk + tg + 4]);
            }
            #pragma unroll
            for (int ni = 0; ni < 4; ni++) {
                int n = wn * 32 + ni * 8 + gid;
                bf[ni][0] = tf32_bits(B[kk + tg    ][n]);
                bf[ni][1] = tf32_bits(B[kk + tg + 4][n]);
            }
            #pragma unroll
            for (int mi = 0; mi < 4; mi++)
                #pragma unroll
                for (int ni = 0; ni < 4; ni++)
                    mma_tf32(c[mi][ni], af[mi][0], af[mi][1], af[mi][2], af[mi][3],
                             bf[ni][0], bf[ni][1]);
        }
    }

    #pragma unroll
    for (int mi = 0; mi < 4; mi++) {
        const int m = wm * 64 + mi * 16 + gid;
        const float bi0 = bias[m];
        const float bi1 = bias[m + 8];
        #pragma unroll
        for (int ni = 0; ni < 4; ni++) {
            int col = n0 + wn * 32 + ni * 8 + tg * 2;
            float2 v0, v1;
            if (rnd) {
                v0 = make_float2(to_tf32(c[mi][ni][0] + bi0), to_tf32(c[mi][ni][1] + bi0));
                v1 = make_float2(to_tf32(c[mi][ni][2] + bi1), to_tf32(c[mi][ni][3] + bi1));
            } else {
                v0 = make_float2(c[mi][ni][0] + bi0, c[mi][ni][1] + bi0);
                v1 = make_float2(c[mi][ni][2] + bi1, c[mi][ni][3] + bi1);
            }
            *(float2*)&dst[(size_t)m * NN + col]       = v0;
            *(float2*)&dst[(size_t)(m + 8) * NN + col] = v1;
        }
    }
}

// ---------------------------------------------------------------------------
// zero g_z
// ---------------------------------------------------------------------------
__global__ void zero_z_kernel() {
    int i = blockIdx.x * 256 + threadIdx.x;
    if (i < BV * NN) g_z[i] = 0.f;
}

// ---------------------------------------------------------------------------
// scores (tf32 mma): S = QtK; epilogue writes bf16 exp(S) + atomic row sums
// ---------------------------------------------------------------------------
__global__ __launch_bounds__(256) void scores_mma_kernel()
{
    const int b = blockIdx.z;
    const float* Ag = g_q + (size_t)b * CQ * NN;
    const float* Bg = g_k + (size_t)b * CQ * NN;
    __nv_bfloat16* Pg = g_pb + (size_t)b * NN * NN;
    const int m0 = blockIdx.y * BM, n0 = blockIdx.x * BN;

    __shared__ __align__(16) float As[2][16][SKP];
    __shared__ __align__(16) float Bs[2][16][SKP];

    const int tid  = threadIdx.x;
    const int lane = tid & 31;
    const int gid  = lane >> 2, tg = lane & 3;
    const int wid  = tid >> 5;
    const int wm   = wid >> 2;   // 0..1
    const int wn   = wid & 3;    // 0..3

    float c[4][4][4];
    #pragma unroll
    for (int i = 0; i < 4; i++)
        #pragma unroll
        for (int j = 0; j < 4; j++)
            #pragma unroll
            for (int r = 0; r < 4; r++) c[i][j][r] = 0.f;

    auto load_tile = [&](int k0, int s) {
        #pragma unroll
        for (int i = 0; i < 2; i++) {
            int idx = tid * 2 + i;
            int r = idx >> 5, c4 = (idx & 31) * 4;
            cp16(su32(&As[s][r][c4]), Ag + (size_t)(k0 + r) * NN + m0 + c4);
            cp16(su32(&Bs[s][r][c4]), Bg + (size_t)(k0 + r) * NN + n0 + c4);
        }
        cp_commit();
    };

    const int T = CQ / 16;  // 8
    load_tile(0, 0);
    for (int it = 0; it < T; ++it) {
        cp_wait<0>();
        __syncthreads();
        if (it + 1 < T) load_tile((it + 1) * 16, (it + 1) & 1);
        const float (*A)[SKP] = As[it & 1];
        const float (*B)[SKP] = Bs[it & 1];
        #pragma unroll
        for (int kk = 0; kk < 16; kk += 8) {
            uint32_t af[4][4], bf[4][2];
            #pragma unroll
            for (int mi = 0; mi < 4; mi++) {
                int m = wm * 64 + mi * 16 + gid;
                af[mi][0] = __float_as_uint(A[kk + tg    ][m]);
                af[mi][1] = __float_as_uint(A[kk + tg    ][m + 8]);
                af[mi][2] = __float_as_uint(A[kk + tg + 4][m]);
                af[mi][3] = __float_as_uint(A[kk + tg + 4][m + 8]);
            }
            #pragma unroll
            for (int ni = 0; ni < 4; ni++) {
                int n = wn * 32 + ni * 8 + gid;
                bf[ni][0] = __float_as_uint(B[kk + tg    ][n]);
                bf[ni][1] = __float_as_uint(B[kk + tg + 4][n]);
            }
            #pragma unroll
            for (int mi = 0; mi < 4; mi++)
                #pragma unroll
                for (int ni = 0; ni < 4; ni++)
                    mma_tf32(c[mi][ni], af[mi][0], af[mi][1], af[mi][2], af[mi][3],
                             bf[ni][0], bf[ni][1]);
        }
    }

    // epilogue: exp -> bf16 store, warp-reduced row sums -> atomicAdd
    #pragma unroll
    for (int mi = 0; mi < 4; mi++) {
        const int row = m0 + wm * 64 + mi * 16 + gid;
        float rs0 = 0.f, rs1 = 0.f;
        #pragma unroll
        for (int ni = 0; ni < 4; ni++) {
            const int col = n0 + wn * 32 + ni * 8 + tg * 2;
            float e00 = __expf(c[mi][ni][0]);
            float e01 = __expf(c[mi][ni][1]);
            float e10 = __expf(c[mi][ni][2]);
            float e11 = __expf(c[mi][ni][3]);
            __nv_bfloat162 p0 = __float22bfloat162_rn(make_float2(e00, e01));
            __nv_bfloat162 p1 = __float22bfloat162_rn(make_float2(e10, e11));
            *(__nv_bfloat162*)&Pg[(size_t)row * NN + col]       = p0;
            *(__nv_bfloat162*)&Pg[(size_t)(row + 8) * NN + col] = p1;
            rs0 += __bfloat162float(p0.x) + __bfloat162float(p0.y);
            rs1 += __bfloat162float(p1.x) + __bfloat162float(p1.y);
        }
        rs0 += __shfl_xor_sync(0xffffffffu, rs0, 1);
        rs0 += __shfl_xor_sync(0xffffffffu, rs0, 2);
        rs1 += __shfl_xor_sync(0xffffffffu, rs1, 1);
        rs1 += __shfl_xor_sync(0xffffffffu, rs1, 2);
        if (tg == 0) {
            atomicAdd(&g_z[(size_t)b * NN + row],     rs0);
            atomicAdd(&g_z[(size_t)b * NN + row + 8], rs1);
        }
    }
}

// ---------------------------------------------------------------------------
// vscale: g_vb[b,c,i] = bf16( g_v[b,c,i] / Z[b,i] )
// ---------------------------------------------------------------------------
__global__ __launch_bounds__(256) void vscale_kernel() {
    size_t t = (size_t)blockIdx.x * 256 + threadIdx.x;
    size_t base = t * 4;  // over BV*CC*NN
    float4 v = *(const float4*)&g_v[base];
    size_t i = base % NN;
    size_t b = base / ((size_t)CC * NN);
    const float* z = &g_z[b * NN + i];
    __nv_bfloat162 o0 = __float22bfloat162_rn(
        make_float2(__fdividef(v.x, z[0]), __fdividef(v.y, z[1])));
    __nv_bfloat162 o1 = __float22bfloat162_rn(
        make_float2(__fdividef(v.z, z[2]), __fdividef(v.w, z[3])));
    *(__nv_bfloat162*)&g_vb[base]     = o0;
    *(__nv_bfloat162*)&g_vb[base + 2] = o1;
}

// ---------------------------------------------------------------------------
// av (bf16 mma): out[b,c,j] = gamma * sum_i vb[c,i] * pb[i,j] + x[b,c,j]
// ---------------------------------------------------------------------------
#define A_PAD 40    // bf16 elems per A smem row
#define B_PAD 136   // bf16 elems per B smem row
__global__ __launch_bounds__(256) void av_bf16_kernel(
    const float* __restrict__ x, const float* __restrict__ gamma,
    float* __restrict__ out)
{
    const int b = blockIdx.z;
    const __nv_bfloat16* Ag = g_vb + (size_t)b * CC * NN;
    const __nv_bfloat16* Bg = g_pb + (size_t)b * NN * NN;
    const float* Xg = x + (size_t)b * CC * NN;
    float*       Cg = out + (size_t)b * CC * NN;
    const int m0 = blockIdx.y * BM, n0 = blockIdx.x * BN;

    __shared__ __align__(16) __nv_bfloat16 Asm[2][128][A_PAD];
    __shared__ __align__(16) __nv_bfloat16 Bsm[2][32][B_PAD];

    const int tid  = threadIdx.x;
    const int lane = tid & 31;
    const int gid  = lane >> 2, tg = lane & 3;
    const int wid  = tid >> 5;
    const int wm   = wid >> 2;   // 0..1
    const int wn   = wid & 3;    // 0..3

    const int fr_row = (lane & 7) + ((lane >> 3) & 1) * 8;  // 0..15
    const int fr_hi  = ((lane >> 4) & 1) * 8;               // 0 or 8

    float c[4][4][4];
    #pragma unroll
    for (int i = 0; i < 4; i++)
        #pragma unroll
        for (int j = 0; j < 4; j++)
            #pragma unroll
            for (int r = 0; r < 4; r++) c[i][j][r] = 0.f;

    auto load_tile = [&](int k0, int s) {
        #pragma unroll
        for (int i = 0; i < 2; i++) {
            int idx = tid * 2 + i;            // 0..511
            int am = idx >> 2, aq = (idx & 3) * 8;
            cp16(su32(&Asm[s][am][aq]), Ag + (size_t)(m0 + am) * NN + k0 + aq);
            int br = idx >> 4, bc = (idx & 15) * 8;
            cp16(su32(&Bsm[s][br][bc]), Bg + (size_t)(k0 + br) * NN + n0 + bc);
        }
        cp_commit();
    };

    const int T = NN / 32;  // 128
    load_tile(0, 0);
    for (int it = 0; it < T; ++it) {
        cp_wait<0>();
        __syncthreads();
        if (it + 1 < T) load_tile((it + 1) * 32, (it + 1) & 1);
        const __nv_bfloat16 (*A)[A_PAD] = Asm[it & 1];
        const __nv_bfloat16 (*B)[B_PAD] = Bsm[it & 1];
        #pragma unroll
        for (int kk = 0; kk < 32; kk += 16) {
            uint32_t af[4][4], bfg[4][2];
            #pragma unroll
            for (int mi = 0; mi < 4; mi++) {
                unsigned ad = su32(&A[wm * 64 + mi * 16 + fr_row][kk + fr_hi]);
                ldsm_x4(af[mi][0], af[mi][1], af[mi][2], af[mi][3], ad);
            }
            #pragma unroll
            for (int nj = 0; nj < 2; nj++) {
                unsigned bd = su32(&B[kk + fr_row][wn * 32 + nj * 16 + fr_hi]);
                ldsm_x4_t(bfg[2 * nj][0], bfg[2 * nj][1],
                          bfg[2 * nj + 1][0], bfg[2 * nj + 1][1], bd);
            }
            #pragma unroll
            for (int mi = 0; mi < 4; mi++)
                #pragma unroll
                for (int ni = 0; ni < 4; ni++)
                    mma_bf16(c[mi][ni], af[mi][0], af[mi][1], af[mi][2], af[mi][3],
                             bfg[ni][0], bfg[ni][1]);
        }
    }

    const float g = gamma[0];
    #pragma unroll
    for (int mi = 0; mi < 4; mi++) {
        #pragma unroll
        for (int ni = 0; ni < 4; ni++) {
            int row = m0 + wm * 64 + mi * 16 + gid;
            int col = n0 + wn * 32 + ni * 8 + tg * 2;
            size_t o0 = (size_t)row * NN + col;
            size_t o1 = (size_t)(row + 8) * NN + col;
            float2 x0 = *(const float2*)&Xg[o0];
            float2 x1 = *(const float2*)&Xg[o1];
            float2 r0 = {g * c[mi][ni][0] + x0.x, g * c[mi][ni][1] + x0.y};
            float2 r1 = {g * c[mi][ni][2] + x1.x, g * c[mi][ni][3] + x1.y};
            *(float2*)&Cg[o0] = r0;
            *(float2*)&Cg[o1] = r1;
        }
    }
}

// ---------------------------------------------------------------------------
extern "C" void kernel_launch(void* const* d_in, const int* in_sizes, int n_in,
                              void* d_out, int out_size)
{
    const float* x     = (const float*)d_in[0];
    const float* wq    = (const float*)d_in[1];
    const float* bq    = (const float*)d_in[2];
    const float* wk    = (const float*)d_in[3];
    const float* bk    = (const float*)d_in[4];
    const float* wv    = (const float*)d_in[5];
    const float* bv    = (const float*)d_in[6];
    const float* gamma = (const float*)d_in[7];
    float* out = (float*)d_out;

    zero_z_kernel<<<(BV * NN + 255) / 256, 256>>>();
    proj_mma_kernel<<<dim3(NN / BN, 4, BV), 256>>>(wq, bq, wk, bk, wv, bv, x);
    scores_mma_kernel<<<dim3(NN / BN, NN / BM, BV), 256>>>();
    vscale_kernel<<<(BV * CC * NN / 4 + 255) / 256, 256>>>();
    av_bf16_kernel<<<dim3(NN / BN, CC / BM, BV), 256>>>(x, gamma, out);
}